// round 1
// baseline (speedup 1.0000x reference)
#include <cuda_runtime.h>
#include <math.h>

#define Bc 4
#define Sc 2
#define Pc 17
#define Hc 128
#define Wc 128
#define Mc 8
#define Kc 10
#define Cc 34          // (1+TAG)*P = 34 channels
#define HWc 16384
#define PHWc 278528
#define BSc 8
#define DET_BLOCKS 256
#define DET_N (Bc*Sc*Pc*HWc)

// ---------------- scratch (device globals; no allocation allowed) ----------
__device__ double g_det_part[DET_BLOCKS];
__device__ int    g_topi[BSc*Kc];
__device__ float  g_tv[BSc*Kc];
__device__ int    g_pid[BSc*Kc];
__device__ float  g_skel[BSc*Kc*Pc*2];
__device__ double g_pushpull[2];

// E_INV = float(np.e**-1) rounded to f32 by the compiler
#define EINV 0.36787944117144233f

// ============================================================
// Kernel A: detection BCE loss partial sums
// ============================================================
__global__ void det_kernel(const float* __restrict__ preds,
                           const float* __restrict__ gt_masks,
                           const float* __restrict__ gt_heatmaps) {
    int tid = blockIdx.x * blockDim.x + threadIdx.x;
    int stride = gridDim.x * blockDim.x;
    double acc = 0.0;
    for (int f = tid; f < DET_N; f += stride) {
        int hw = f % HWc;
        int t1 = f / HWc;          // (b*S+s)*P + p
        int p  = t1 % Pc;
        int bs = t1 / Pc;          // b*S+s
        int b  = bs / Sc;
        float hmv = preds[((size_t)bs * Cc + p) * HWc + hw];
        float gh  = gt_heatmaps[((size_t)(b * Pc + p)) * HWc + hw];
        float mk  = gt_masks[(size_t)b * HWc + hw];
        float prob = 1.0f / (1.0f + expf(-hmv));
        float x = prob * mk;
        float t = (gh > EINV) ? 1.0f : 0.0f;
        float wgt = 10.0f * t + ((gh < EINV) ? 0.5f : 0.0f);
        float l1 = fmaxf(logf(x), -100.0f);          // clog(x)
        float l2 = fmaxf(logf(1.0f - x), -100.0f);   // clog(1-x)
        float bce = -(t * l1 + (1.0f - t) * l2);
        acc += (double)(wgt * bce);
    }
    __shared__ double sred[256];
    sred[threadIdx.x] = acc;
    __syncthreads();
    for (int o = 128; o > 0; o >>= 1) {
        if (threadIdx.x < o) sred[threadIdx.x] += sred[threadIdx.x + o];
        __syncthreads();
    }
    if (threadIdx.x == 0) g_det_part[blockIdx.x] = sred[0];
}

// ============================================================
// Kernel B: per-(b,s) top-K over prob == top-K over hm (sigmoid monotone)
// ============================================================
__global__ void topk_kernel(const float* __restrict__ preds) {
    int bs = blockIdx.x;                        // 0..7
    const float* base = preds + (size_t)bs * Cc * HWc;   // hm channels 0..P-1 contiguous
    float v[Kc];
    int   ix[Kc];
#pragma unroll
    for (int k = 0; k < Kc; k++) { v[k] = -1e30f; ix[k] = -1; }
    float vmin = -1e30f;
    for (int i = threadIdx.x; i < PHWc; i += blockDim.x) {
        float val = base[i];
        if (val > vmin) {
            int pos = Kc - 1;
            while (pos > 0 && val > v[pos - 1]) {
                v[pos] = v[pos - 1]; ix[pos] = ix[pos - 1]; pos--;
            }
            v[pos] = val; ix[pos] = i;
            vmin = v[Kc - 1];
        }
    }
    __shared__ float sv[256 * Kc];
    __shared__ int   si[256 * Kc];
    for (int k = 0; k < Kc; k++) {
        sv[threadIdx.x * Kc + k] = v[k];
        si[threadIdx.x * Kc + k] = ix[k];
    }
    __syncthreads();
    __shared__ float rv[256];
    __shared__ int   ri[256];
    for (int sel = 0; sel < Kc; sel++) {
        float bm = -2e30f; int bi = 0;
        for (int j = threadIdx.x; j < 256 * Kc; j += 256) {
            if (sv[j] > bm) { bm = sv[j]; bi = j; }
        }
        rv[threadIdx.x] = bm; ri[threadIdx.x] = bi;
        __syncthreads();
        for (int o = 128; o > 0; o >>= 1) {
            if (threadIdx.x < o && rv[threadIdx.x + o] > rv[threadIdx.x]) {
                rv[threadIdx.x] = rv[threadIdx.x + o];
                ri[threadIdx.x] = ri[threadIdx.x + o];
            }
            __syncthreads();
        }
        if (threadIdx.x == 0) {
            g_topi[bs * Kc + sel] = si[ri[0]];
            sv[ri[0]] = -3e30f;
        }
        __syncthreads();
    }
}

// ============================================================
// Kernel C: tv + person_ids + tag push/pull loss
// ============================================================
__global__ void aux_kernel(const float* __restrict__ preds,
                           const float* __restrict__ gt_sk,
                           const int* __restrict__ gt_kp) {
    int tid = threadIdx.x;

    // --- tv & person_ids: threads 0..79 (one per (bs,k)) ---
    if (tid < BSc * Kc) {
        int bs = tid / Kc;
        int b  = bs / Sc;
        int i  = g_topi[tid];
        int p  = i / HWc;
        int hw = i % HWc;
        int xi = hw / Wc;
        int yi = hw % Wc;
        // tag value at top-k location (TAG=1; tag channels start at P)
        g_tv[tid] = preds[((size_t)bs * Cc + Pc) * HWc + i];
        // argmin_m dist  (replicates reference's dvec = vispen + sk[1:3] - (xi,yi))
        float best = 3.4e38f; int bestm = 0;
        for (int m = 0; m < Mc; m++) {
            const float* sk = gt_sk + ((b * Mc + m) * Pc + p) * 3;
            float vp = (sk[2] == 1.0f) ? 256.0f : 0.0f;   // max_dist = H+W
            float d0 = vp + sk[1] - (float)xi;
            float d1 = vp + sk[2] - (float)yi;
            float d  = sqrtf(d0 * d0 + d1 * d1 + 1e-12f);
            if (d < best) { best = d; bestm = m; }
        }
        g_pid[tid] = bestm;
    }

    // --- tag push/pull: threads 96..103, one per (b,s) ---
    __shared__ float spush[BSc], spull[BSc];
    if (tid >= 96 && tid < 96 + BSc) {
        int bs = tid - 96;
        int b  = bs / Sc;
        const float* tb = preds + ((size_t)bs * Cc + Pc) * HWc;  // flat tags, PHW
        float mean[Mc], validf[Mc], pullpp[Mc];
        float num = 0.0f;
        for (int m = 0; m < Mc; m++) {
            float gv[Pc], vv[Pc];
            float cnt = 0.0f, sum = 0.0f;
            for (int p = 0; p < Pc; p++) {
                const int* kp = gt_kp + (((b * Mc + m) * Pc + p) * 2);
                int idx = kp[0];
                float vis = (kp[1] > 0) ? 1.0f : 0.0f;
                float g = tb[idx];
                gv[p] = g; vv[p] = vis;
                cnt += vis; sum += vis * g;
            }
            float valid = (cnt > 0.0f) ? 1.0f : 0.0f;
            float safe  = fmaxf(cnt, 1.0f);
            float mt = sum / safe;
            mean[m] = mt; validf[m] = valid;
            float pp = 0.0f;
            for (int p = 0; p < Pc; p++) {
                float d = gv[p] - mt;
                pp += d * d * vv[p];
            }
            pullpp[m] = pp / safe;   // /(safe*TAG), TAG=1
            num += valid;
        }
        float pull = 0.0f;
        for (int m = 0; m < Mc; m++) pull += pullpp[m] * validf[m];
        pull /= (num + 1e-6f);
        float pmsum = 0.0f;
        for (int i2 = 0; i2 < Mc; i2++)
            for (int j = 0; j < Mc; j++) {
                float d = mean[i2] - mean[j];
                pmsum += expf(-d * d) * validf[i2] * validf[j];
            }
        float push = (pmsum - num) / ((num - 1.0f) * num + 1e-6f) * 0.5f;
        spush[bs] = push; spull[bs] = pull;
    }
    __syncthreads();
    if (tid == 0) {
        double sp = 0.0, sl = 0.0;
        for (int j = 0; j < BSc; j++) { sp += (double)spush[j]; sl += (double)spull[j]; }
        g_pushpull[0] = sp;
        g_pushpull[1] = sl;
    }
}

// ============================================================
// Kernel D: per-(b,s,p) plane, one warp per k: 2-pass softmax + coord sums
// ============================================================
__global__ void __launch_bounds__(320) softmax_kernel(const float* __restrict__ preds) {
    int p  = blockIdx.x;
    int bs = blockIdx.y;
    int warp = threadIdx.x >> 5;   // == k (0..9)
    int lane = threadIdx.x & 31;
    const float* hmp = preds + ((size_t)bs * Cc + p) * HWc;
    const float* tgp = hmp + (size_t)Pc * HWc;   // tag channel P+p
    float tv = g_tv[bs * Kc + warp];

    // pass 1: max of logits
    float m = -1e30f;
    for (int i = lane; i < HWc; i += 32) {
        float d = tgp[i] - tv;
        float l = fmaf(3.0f, hmp[i], -d * d * 12.5f);   // SF*hm - aff/(2*sigma^2)
        m = fmaxf(m, l);
    }
#pragma unroll
    for (int o = 16; o > 0; o >>= 1) m = fmaxf(m, __shfl_xor_sync(0xffffffffu, m, o));

    // pass 2: sums
    float se = 0.0f, sx = 0.0f, sy = 0.0f;
    for (int i = lane; i < HWc; i += 32) {
        float d = tgp[i] - tv;
        float l = fmaf(3.0f, hmp[i], -d * d * 12.5f);
        float e = expf(l - m);
        se += e;
        sx += e * (float)(i >> 7);    // h coordinate (row)
        sy += e * (float)(i & 127);   // w coordinate (col)
    }
#pragma unroll
    for (int o = 16; o > 0; o >>= 1) {
        se += __shfl_xor_sync(0xffffffffu, se, o);
        sx += __shfl_xor_sync(0xffffffffu, sx, o);
        sy += __shfl_xor_sync(0xffffffffu, sy, o);
    }
    if (lane == 0) {
        int t = (bs * Kc + warp) * Pc + p;
        g_skel[2 * t]     = sx / se;
        g_skel[2 * t + 1] = sy / se;
    }
}

// ============================================================
// Kernel E: Huber + deterministic final combine
// ============================================================
__global__ void final_kernel(const float* __restrict__ gt_sk, float* __restrict__ out) {
    int tid = threadIdx.x;
    double acc = 0.0;
    for (int t = tid; t < BSc * Kc * Pc; t += 256) {
        int p   = t % Pc;
        int bsk = t / Pc;
        int bs  = bsk / Kc;
        int b   = bs / Sc;
        int pid = g_pid[bsk];
        const float* sk = gt_sk + ((b * Mc + pid) * Pc + p) * 3;
        float ex = sk[0] - g_skel[2 * t];
        float ey = sk[1] - g_skel[2 * t + 1];
        float err = sqrtf(ex * ex + ey * ey + 1e-12f) * ((sk[2] > 0.0f) ? 1.0f : 0.0f);
        float a = fabsf(err);
        float hub = (a < 0.1f) ? (err * err) : (0.1f * (a - 0.05f));
        acc += (double)hub;
    }
    __shared__ double sred[256];
    sred[tid] = acc;
    __syncthreads();
    for (int o = 128; o > 0; o >>= 1) {
        if (tid < o) sred[tid] += sred[tid + o];
        __syncthreads();
    }
    if (tid == 0) {
        double det = 0.0;
        for (int j = 0; j < DET_BLOCKS; j++) det += g_det_part[j];
        det /= (double)DET_N;
        double total = g_pushpull[0] / 8.0
                     + g_pushpull[1] / 8.0
                     + det
                     + 10.0 * sred[0] / (double)(BSc * Kc * Pc);
        out[0] = (float)total;
    }
}

// ============================================================
extern "C" void kernel_launch(void* const* d_in, const int* in_sizes, int n_in,
                              void* d_out, int out_size) {
    const float* preds       = (const float*)d_in[0];
    const float* gt_masks    = (const float*)d_in[1];
    const float* gt_heatmaps = (const float*)d_in[2];
    const float* gt_sk       = (const float*)d_in[3];
    const int*   gt_kp       = (const int*)d_in[4];

    det_kernel<<<DET_BLOCKS, 256>>>(preds, gt_masks, gt_heatmaps);
    topk_kernel<<<BSc, 256>>>(preds);
    aux_kernel<<<1, 128>>>(preds, gt_sk, gt_kp);
    softmax_kernel<<<dim3(Pc, BSc), 320>>>(preds);
    final_kernel<<<1, 256>>>(gt_sk, (float*)d_out);
}

// round 2
// speedup vs baseline: 6.4075x; 6.4075x over previous
#include <cuda_runtime.h>
#include <math.h>

#define Bc 4
#define Sc 2
#define Pc 17
#define Hc 128
#define Wc 128
#define Mc 8
#define Kc 10
#define Cc 34          // (1+TAG)*P = 34 channels
#define HWc 16384
#define PHWc 278528
#define BSc 8
#define DET_BLOCKS 256
#define DET_N (Bc*Sc*Pc*HWc)
#define NCH 34
#define CHUNK 8192     // NCH*CHUNK == PHWc

// ---------------- scratch (device globals; no allocation allowed) ----------
__device__ double g_det_part[DET_BLOCKS];
__device__ float  g_cand_v[BSc*NCH*Kc];
__device__ int    g_cand_i[BSc*NCH*Kc];
__device__ int    g_topi[BSc*Kc];
__device__ float  g_tv[BSc*Kc];
__device__ int    g_pid[BSc*Kc];
__device__ float  g_skel[BSc*Kc*Pc*2];
__device__ double g_pushpull[2];

#define EINV 0.36787944117144233f

// ============================================================
// Kernel A: detection BCE loss partial sums (fast-math transcendentals)
// ============================================================
__global__ void det_kernel(const float* __restrict__ preds,
                           const float* __restrict__ gt_masks,
                           const float* __restrict__ gt_heatmaps) {
    int tid = blockIdx.x * blockDim.x + threadIdx.x;
    int stride = gridDim.x * blockDim.x;
    double acc = 0.0;
    for (int f = tid; f < DET_N; f += stride) {
        int hw = f % HWc;
        int t1 = f / HWc;
        int p  = t1 % Pc;
        int bs = t1 / Pc;
        int b  = bs / Sc;
        float hmv = preds[((size_t)bs * Cc + p) * HWc + hw];
        float gh  = gt_heatmaps[((size_t)(b * Pc + p)) * HWc + hw];
        float mk  = gt_masks[(size_t)b * HWc + hw];
        float prob = __fdividef(1.0f, 1.0f + __expf(-hmv));
        float x = prob * mk;
        float t = (gh > EINV) ? 1.0f : 0.0f;
        float wgt = 10.0f * t + ((gh < EINV) ? 0.5f : 0.0f);
        float l1 = fmaxf(__logf(x), -100.0f);
        float l2 = fmaxf(__logf(1.0f - x), -100.0f);
        float bce = -(t * l1 + (1.0f - t) * l2);
        acc += (double)(wgt * bce);
    }
    __shared__ double sred[256];
    sred[threadIdx.x] = acc;
    __syncthreads();
    for (int o = 128; o > 0; o >>= 1) {
        if (threadIdx.x < o) sred[threadIdx.x] += sred[threadIdx.x + o];
        __syncthreads();
    }
    if (threadIdx.x == 0) g_det_part[blockIdx.x] = sred[0];
}

// ============================================================
// branchless register-resident top-10 insertion (fully unrolled)
// ============================================================
__device__ __forceinline__ void insert10(float val, int idx, float* v, int* ix) {
    if (val <= v[Kc - 1]) return;
#pragma unroll
    for (int k = Kc - 1; k > 0; k--) {
        bool shift = val > v[k - 1];
        bool place = val > v[k];          // uses old v[k]
        float nv = shift ? v[k - 1] : (place ? val : v[k]);
        int   ni = shift ? ix[k - 1] : (place ? idx : ix[k]);
        v[k] = nv; ix[k] = ni;
    }
    if (val > v[0]) { v[0] = val; ix[0] = idx; }
}

// ============================================================
// Kernel B1: per-(bs,chunk) top-10 candidates (float4 loads, wide grid)
// ============================================================
__global__ void topk1_kernel(const float* __restrict__ preds) {
    int ch = blockIdx.x;            // 0..33
    int bs = blockIdx.y;            // 0..7
    int tid = threadIdx.x;
    const float4* __restrict__ base4 =
        (const float4*)(preds + (size_t)bs * Cc * HWc + (size_t)ch * CHUNK);
    int i0 = ch * CHUNK;

    float v[Kc]; int ix[Kc];
#pragma unroll
    for (int k = 0; k < Kc; k++) { v[k] = -3.0e38f; ix[k] = -1; }

#pragma unroll
    for (int j = 0; j < 8; j++) {
        int idx4 = tid + 256 * j;
        float4 f = base4[idx4];
        int e = i0 + 4 * idx4;
        insert10(f.x, e + 0, v, ix);
        insert10(f.y, e + 1, v, ix);
        insert10(f.z, e + 2, v, ix);
        insert10(f.w, e + 3, v, ix);
    }

    __shared__ float sv[256 * Kc];
    __shared__ int   si[256 * Kc];
#pragma unroll
    for (int k = 0; k < Kc; k++) {
        sv[tid * Kc + k] = v[k];
        si[tid * Kc + k] = ix[k];
    }
    __syncthreads();
    __shared__ float rv[256];
    __shared__ int   ri[256];
    for (int sel = 0; sel < Kc; sel++) {
        float bm = -3.2e38f; int bi = 0;
        for (int j = tid; j < 256 * Kc; j += 256)
            if (sv[j] > bm) { bm = sv[j]; bi = j; }
        rv[tid] = bm; ri[tid] = bi;
        __syncthreads();
        for (int o = 128; o > 0; o >>= 1) {
            if (tid < o && rv[tid + o] > rv[tid]) {
                rv[tid] = rv[tid + o];
                ri[tid] = ri[tid + o];
            }
            __syncthreads();
        }
        if (tid == 0) {
            int slot = (bs * NCH + ch) * Kc + sel;
            g_cand_v[slot] = rv[0];
            g_cand_i[slot] = si[ri[0]];
            sv[ri[0]] = -3.3e38f;
        }
        __syncthreads();
    }
}

// ============================================================
// Kernel C: top-K merge + tv + person_ids + tag push/pull
// ============================================================
__global__ void aux_kernel(const float* __restrict__ preds,
                           const float* __restrict__ gt_sk,
                           const int* __restrict__ gt_kp) {
    int tid = threadIdx.x;
    int w = tid >> 5;
    int lane = tid & 31;
    __shared__ float spush[BSc], spull[BSc];

    // --- phase A (warps 0..7): merge 340 candidates -> top-10 per bs ---
    if (w < BSc) {
        int bs = w;
        float cv[11]; int ci[11];
#pragma unroll
        for (int j = 0; j < 11; j++) {
            int c = lane * 11 + j;
            if (c < NCH * Kc) {
                cv[j] = g_cand_v[bs * NCH * Kc + c];
                ci[j] = g_cand_i[bs * NCH * Kc + c];
            } else { cv[j] = -3.3e38f; ci[j] = -1; }
        }
        for (int sel = 0; sel < Kc; sel++) {
            float bv = -3.35e38f; int bj = 0;
#pragma unroll
            for (int j = 0; j < 11; j++)
                if (cv[j] > bv) { bv = cv[j]; bj = j; }
            int bidx = ci[bj];
            int wown = lane, wslot = bj;
#pragma unroll
            for (int o = 16; o > 0; o >>= 1) {
                float ov = __shfl_xor_sync(0xffffffffu, bv, o);
                int   oi = __shfl_xor_sync(0xffffffffu, bidx, o);
                int   oo = __shfl_xor_sync(0xffffffffu, wown, o);
                int   os = __shfl_xor_sync(0xffffffffu, wslot, o);
                if (ov > bv) { bv = ov; bidx = oi; wown = oo; wslot = os; }
            }
            if (lane == wown) cv[wslot] = -3.3e38f;
            if (lane == 0) g_topi[bs * Kc + sel] = bidx;
        }
    }

    // --- phase A' (warp 4..: threads 128..135): tag push/pull (independent) ---
    if (tid >= 128 && tid < 128 + BSc) {
        int bs = tid - 128;
        int b  = bs / Sc;
        const float* tb = preds + ((size_t)bs * Cc + Pc) * HWc;
        float mean[Mc], validf[Mc], pullpp[Mc];
        float num = 0.0f;
        for (int m = 0; m < Mc; m++) {
            float gv[Pc], vv[Pc];
            float cnt = 0.0f, sum = 0.0f;
#pragma unroll
            for (int p = 0; p < Pc; p++) {
                const int* kp = gt_kp + (((b * Mc + m) * Pc + p) * 2);
                int idx = kp[0];
                float vis = (kp[1] > 0) ? 1.0f : 0.0f;
                float g = tb[idx];
                gv[p] = g; vv[p] = vis;
                cnt += vis; sum += vis * g;
            }
            float valid = (cnt > 0.0f) ? 1.0f : 0.0f;
            float safe  = fmaxf(cnt, 1.0f);
            float mt = sum / safe;
            mean[m] = mt; validf[m] = valid;
            float pp = 0.0f;
#pragma unroll
            for (int p = 0; p < Pc; p++) {
                float d = gv[p] - mt;
                pp += d * d * vv[p];
            }
            pullpp[m] = pp / safe;
            num += valid;
        }
        float pull = 0.0f;
        for (int m = 0; m < Mc; m++) pull += pullpp[m] * validf[m];
        pull /= (num + 1e-6f);
        float pmsum = 0.0f;
        for (int i2 = 0; i2 < Mc; i2++)
            for (int j = 0; j < Mc; j++) {
                float d = mean[i2] - mean[j];
                pmsum += expf(-d * d) * validf[i2] * validf[j];
            }
        float push = (pmsum - num) / ((num - 1.0f) * num + 1e-6f) * 0.5f;
        spush[bs] = push; spull[bs] = pull;
    }
    __syncthreads();

    // --- phase B: tv & person_ids (needs merged g_topi) ---
    if (tid < BSc * Kc) {
        int bs = tid / Kc;
        int b  = bs / Sc;
        int i  = g_topi[tid];
        int p  = i / HWc;
        int hw = i % HWc;
        int xi = hw / Wc;
        int yi = hw % Wc;
        g_tv[tid] = preds[((size_t)bs * Cc + Pc) * HWc + i];
        float best = 3.4e38f; int bestm = 0;
        for (int m = 0; m < Mc; m++) {
            const float* sk = gt_sk + ((b * Mc + m) * Pc + p) * 3;
            float vp = (sk[2] == 1.0f) ? 256.0f : 0.0f;
            float d0 = vp + sk[1] - (float)xi;
            float d1 = vp + sk[2] - (float)yi;
            float d  = sqrtf(d0 * d0 + d1 * d1 + 1e-12f);
            if (d < best) { best = d; bestm = m; }
        }
        g_pid[tid] = bestm;
    }

    if (tid == 192) {
        double sp = 0.0, sl = 0.0;
        for (int j = 0; j < BSc; j++) { sp += (double)spush[j]; sl += (double)spull[j]; }
        g_pushpull[0] = sp;
        g_pushpull[1] = sl;
    }
}

// ============================================================
// Kernel D: single-pass softmax per (b,s,p) plane, one warp per k
// logits bounded (|3*hm| small, aff<=0) -> no max subtraction needed;
// softmax ratio makes the shift cancel exactly.
// ============================================================
__global__ void __launch_bounds__(320) softmax_kernel(const float* __restrict__ preds) {
    int p  = blockIdx.x;
    int bs = blockIdx.y;
    int warp = threadIdx.x >> 5;
    int lane = threadIdx.x & 31;
    const float4* __restrict__ hm4 = (const float4*)(preds + ((size_t)bs * Cc + p) * HWc);
    const float4* __restrict__ tg4 = hm4 + (Pc * HWc / 4);
    float tv = g_tv[bs * Kc + warp];

    const float C1 = 4.328085122666891f;    // 3 * log2(e)
    const float C2 = 18.033688011112047f;   // 12.5 * log2(e)
    float se = 0.0f, sx = 0.0f, sy = 0.0f;
    float y0 = (float)(4 * lane), y1 = y0 + 1.0f, y2 = y0 + 2.0f, y3 = y0 + 3.0f;

#pragma unroll 4
    for (int j = 0; j < 128; j++) {
        float4 h = hm4[lane + 32 * j];
        float4 t = tg4[lane + 32 * j];
        float xf = (float)j;
        float d, q, e;
        d = t.x - tv; q = d * d; e = exp2f(fmaf(h.x, C1, -C2 * q));
        se += e; sx = fmaf(e, xf, sx); sy = fmaf(e, y0, sy);
        d = t.y - tv; q = d * d; e = exp2f(fmaf(h.y, C1, -C2 * q));
        se += e; sx = fmaf(e, xf, sx); sy = fmaf(e, y1, sy);
        d = t.z - tv; q = d * d; e = exp2f(fmaf(h.z, C1, -C2 * q));
        se += e; sx = fmaf(e, xf, sx); sy = fmaf(e, y2, sy);
        d = t.w - tv; q = d * d; e = exp2f(fmaf(h.w, C1, -C2 * q));
        se += e; sx = fmaf(e, xf, sx); sy = fmaf(e, y3, sy);
    }
#pragma unroll
    for (int o = 16; o > 0; o >>= 1) {
        se += __shfl_xor_sync(0xffffffffu, se, o);
        sx += __shfl_xor_sync(0xffffffffu, sx, o);
        sy += __shfl_xor_sync(0xffffffffu, sy, o);
    }
    if (lane == 0) {
        int t = (bs * Kc + warp) * Pc + p;
        float inv = __fdividef(1.0f, se);
        g_skel[2 * t]     = sx * inv;
        g_skel[2 * t + 1] = sy * inv;
    }
}

// ============================================================
// Kernel E: Huber + deterministic final combine
// ============================================================
__global__ void final_kernel(const float* __restrict__ gt_sk, float* __restrict__ out) {
    int tid = threadIdx.x;
    double acc = 0.0;
    for (int t = tid; t < BSc * Kc * Pc; t += 256) {
        int p   = t % Pc;
        int bsk = t / Pc;
        int bs  = bsk / Kc;
        int b   = bs / Sc;
        int pid = g_pid[bsk];
        const float* sk = gt_sk + ((b * Mc + pid) * Pc + p) * 3;
        float ex = sk[0] - g_skel[2 * t];
        float ey = sk[1] - g_skel[2 * t + 1];
        float err = sqrtf(ex * ex + ey * ey + 1e-12f) * ((sk[2] > 0.0f) ? 1.0f : 0.0f);
        float a = fabsf(err);
        float hub = (a < 0.1f) ? (err * err) : (0.1f * (a - 0.05f));
        acc += (double)hub;
    }
    __shared__ double sred[256];
    sred[tid] = acc;
    __syncthreads();
    for (int o = 128; o > 0; o >>= 1) {
        if (tid < o) sred[tid] += sred[tid + o];
        __syncthreads();
    }
    if (tid == 0) {
        double det = 0.0;
        for (int j = 0; j < DET_BLOCKS; j++) det += g_det_part[j];
        det /= (double)DET_N;
        double total = g_pushpull[0] / 8.0
                     + g_pushpull[1] / 8.0
                     + det
                     + 10.0 * sred[0] / (double)(BSc * Kc * Pc);
        out[0] = (float)total;
    }
}

// ============================================================
extern "C" void kernel_launch(void* const* d_in, const int* in_sizes, int n_in,
                              void* d_out, int out_size) {
    const float* preds       = (const float*)d_in[0];
    const float* gt_masks    = (const float*)d_in[1];
    const float* gt_heatmaps = (const float*)d_in[2];
    const float* gt_sk       = (const float*)d_in[3];
    const int*   gt_kp       = (const int*)d_in[4];

    det_kernel<<<DET_BLOCKS, 256>>>(preds, gt_masks, gt_heatmaps);
    topk1_kernel<<<dim3(NCH, BSc), 256>>>(preds);
    aux_kernel<<<1, 256>>>(preds, gt_sk, gt_kp);
    softmax_kernel<<<dim3(Pc, BSc), 320>>>(preds);
    final_kernel<<<1, 256>>>(gt_sk, (float*)d_out);
}

// round 3
// speedup vs baseline: 7.2868x; 1.1372x over previous
#include <cuda_runtime.h>
#include <math.h>

#define Bc 4
#define Sc 2
#define Pc 17
#define Hc 128
#define Wc 128
#define Mc 8
#define Kc 10
#define Cc 34          // (1+TAG)*P
#define HWc 16384
#define PHWc 278528
#define BSc 8
#define DET_N (Bc*Sc*Pc*HWc)
#define NCH 34
#define CHUNK 8192     // NCH*CHUNK == PHWc
#define SG 8           // softmax chunks per plane
#define SCHUNK 2048    // HWc / SG

// ---------------- scratch (device globals) ----------------
__device__ double g_det_part[BSc*NCH];
__device__ float  g_cand_v[BSc*NCH*Kc];
__device__ int    g_cand_i[BSc*NCH*Kc];
__device__ int    g_topi[BSc*Kc];
__device__ float  g_tv[BSc*Kc];
__device__ int    g_pid[BSc*Kc];
__device__ float  g_spart[BSc*Pc*SG*30];
__device__ double g_pushpull[2];

#define EINV 0.36787944117144233f

// branchless register-resident top-10 insertion
__device__ __forceinline__ void insert10(float val, int idx, float* v, int* ix) {
    if (val <= v[Kc - 1]) return;
#pragma unroll
    for (int k = Kc - 1; k > 0; k--) {
        bool shift = val > v[k - 1];
        bool place = val > v[k];
        float nv = shift ? v[k - 1] : (place ? val : v[k]);
        int   ni = shift ? ix[k - 1] : (place ? idx : ix[k]);
        v[k] = nv; ix[k] = ni;
    }
    if (val > v[0]) { v[0] = val; ix[0] = idx; }
}

// ============================================================
// Kernel 1: fused det-BCE partial + per-chunk top-10 candidates
// grid (NCH, BSc); each block = half a p-plane (8192 elems)
// ============================================================
__global__ void __launch_bounds__(256) scan_kernel(const float* __restrict__ preds,
                                                   const float* __restrict__ gt_masks,
                                                   const float* __restrict__ gt_heatmaps) {
    int ch = blockIdx.x;            // 0..33 : p = ch>>1, half = ch&1
    int bs = blockIdx.y;            // 0..7
    int tid = threadIdx.x;
    int p    = ch >> 1;
    int hw0  = (ch & 1) * CHUNK;
    int b    = bs >> 1;             // bs = b*S+s

    const float4* __restrict__ hm4 = (const float4*)(preds + ((size_t)bs * Cc + p) * HWc + hw0);
    const float4* __restrict__ gh4 = (const float4*)(gt_heatmaps + ((size_t)(b * Pc + p)) * HWc + hw0);
    const float4* __restrict__ mk4 = (const float4*)(gt_masks + (size_t)b * HWc + hw0);
    int i0 = ch * CHUNK;

    float v[Kc]; int ix[Kc];
#pragma unroll
    for (int k = 0; k < Kc; k++) { v[k] = -3.0e38f; ix[k] = -1; }
    double acc = 0.0;

#pragma unroll
    for (int j = 0; j < 8; j++) {
        int idx4 = tid + 256 * j;
        float4 f = hm4[idx4];
        float4 g = gh4[idx4];
        float4 m = mk4[idx4];
        int e = i0 + 4 * idx4;
        insert10(f.x, e + 0, v, ix);
        insert10(f.y, e + 1, v, ix);
        insert10(f.z, e + 2, v, ix);
        insert10(f.w, e + 3, v, ix);
        float hs[4] = {f.x, f.y, f.z, f.w};
        float gs[4] = {g.x, g.y, g.z, g.w};
        float ms[4] = {m.x, m.y, m.z, m.w};
#pragma unroll
        for (int c = 0; c < 4; c++) {
            float prob = 1.0f / (1.0f + expf(-hs[c]));
            float x = prob * ms[c];
            if (gs[c] > EINV) {
                float l1 = fmaxf(logf(x), -100.0f);
                acc += (double)(-10.0f * l1);
            } else if (gs[c] < EINV) {
                float l2 = fmaxf(logf(1.0f - x), -100.0f);
                acc += (double)(-0.5f * l2);
            }
        }
    }

    // det block reduction
    __shared__ double dred[256];
    dred[tid] = acc;
    __syncthreads();
    for (int o = 128; o > 0; o >>= 1) {
        if (tid < o) dred[tid] += dred[tid + o];
        __syncthreads();
    }
    if (tid == 0) g_det_part[bs * NCH + ch] = dred[0];

    // top-10 selection over 2560 thread-candidates
    __shared__ float sv[256 * Kc];
    __shared__ int   si[256 * Kc];
#pragma unroll
    for (int k = 0; k < Kc; k++) {
        sv[tid * Kc + k] = v[k];
        si[tid * Kc + k] = ix[k];
    }
    __syncthreads();
    __shared__ float rv[256];
    __shared__ int   ri[256];
    for (int sel = 0; sel < Kc; sel++) {
        float bm = -3.2e38f; int bi = 0;
        for (int j = tid; j < 256 * Kc; j += 256)
            if (sv[j] > bm) { bm = sv[j]; bi = j; }
        rv[tid] = bm; ri[tid] = bi;
        __syncthreads();
        for (int o = 128; o > 0; o >>= 1) {
            if (tid < o && rv[tid + o] > rv[tid]) {
                rv[tid] = rv[tid + o];
                ri[tid] = ri[tid + o];
            }
            __syncthreads();
        }
        if (tid == 0) {
            int slot = (bs * NCH + ch) * Kc + sel;
            g_cand_v[slot] = rv[0];
            g_cand_i[slot] = si[ri[0]];
            sv[ri[0]] = -3.3e38f;
        }
        __syncthreads();
    }
}

// ============================================================
// Kernel 2: top-K merge + tv + person_ids + tag push/pull
// ============================================================
__global__ void aux_kernel(const float* __restrict__ preds,
                           const float* __restrict__ gt_sk,
                           const int* __restrict__ gt_kp) {
    int tid = threadIdx.x;
    int w = tid >> 5;
    int lane = tid & 31;
    __shared__ float spush[BSc], spull[BSc];

    // merge 340 candidates -> top-10 per bs (warps 0..7)
    if (w < BSc) {
        int bs = w;
        float cv[11]; int ci[11];
#pragma unroll
        for (int j = 0; j < 11; j++) {
            int c = lane * 11 + j;
            if (c < NCH * Kc) {
                cv[j] = g_cand_v[bs * NCH * Kc + c];
                ci[j] = g_cand_i[bs * NCH * Kc + c];
            } else { cv[j] = -3.3e38f; ci[j] = -1; }
        }
        for (int sel = 0; sel < Kc; sel++) {
            float bv = -3.35e38f; int bj = 0;
#pragma unroll
            for (int j = 0; j < 11; j++)
                if (cv[j] > bv) { bv = cv[j]; bj = j; }
            int bidx = ci[bj];
            int wown = lane, wslot = bj;
#pragma unroll
            for (int o = 16; o > 0; o >>= 1) {
                float ov = __shfl_xor_sync(0xffffffffu, bv, o);
                int   oi = __shfl_xor_sync(0xffffffffu, bidx, o);
                int   oo = __shfl_xor_sync(0xffffffffu, wown, o);
                int   os = __shfl_xor_sync(0xffffffffu, wslot, o);
                if (ov > bv) { bv = ov; bidx = oi; wown = oo; wslot = os; }
            }
            if (lane == wown) cv[wslot] = -3.3e38f;
            if (lane == 0) g_topi[bs * Kc + sel] = bidx;
        }
    }

    // tag push/pull (threads 128..135, one per bs)
    if (tid >= 128 && tid < 128 + BSc) {
        int bs = tid - 128;
        int b  = bs / Sc;
        const float* tb = preds + ((size_t)bs * Cc + Pc) * HWc;
        float mean[Mc], validf[Mc], pullpp[Mc];
        float num = 0.0f;
        for (int m = 0; m < Mc; m++) {
            float gv[Pc], vv[Pc];
            float cnt = 0.0f, sum = 0.0f;
#pragma unroll
            for (int p = 0; p < Pc; p++) {
                const int* kp = gt_kp + (((b * Mc + m) * Pc + p) * 2);
                int idx = kp[0];
                float vis = (kp[1] > 0) ? 1.0f : 0.0f;
                float g = tb[idx];
                gv[p] = g; vv[p] = vis;
                cnt += vis; sum += vis * g;
            }
            float valid = (cnt > 0.0f) ? 1.0f : 0.0f;
            float safe  = fmaxf(cnt, 1.0f);
            float mt = sum / safe;
            mean[m] = mt; validf[m] = valid;
            float pp = 0.0f;
#pragma unroll
            for (int p = 0; p < Pc; p++) {
                float d = gv[p] - mt;
                pp += d * d * vv[p];
            }
            pullpp[m] = pp / safe;
            num += valid;
        }
        float pull = 0.0f;
        for (int m = 0; m < Mc; m++) pull += pullpp[m] * validf[m];
        pull /= (num + 1e-6f);
        float pmsum = 0.0f;
        for (int i2 = 0; i2 < Mc; i2++)
            for (int j = 0; j < Mc; j++) {
                float d = mean[i2] - mean[j];
                pmsum += expf(-d * d) * validf[i2] * validf[j];
            }
        float push = (pmsum - num) / ((num - 1.0f) * num + 1e-6f) * 0.5f;
        spush[bs] = push; spull[bs] = pull;
    }
    __syncthreads();

    // tv & person_ids (needs merged g_topi)
    if (tid < BSc * Kc) {
        int bs = tid / Kc;
        int b  = bs / Sc;
        int i  = g_topi[tid];
        int p  = i / HWc;
        int hw = i % HWc;
        int xi = hw / Wc;
        int yi = hw % Wc;
        g_tv[tid] = preds[((size_t)bs * Cc + Pc) * HWc + i];
        float best = 3.4e38f; int bestm = 0;
        for (int m = 0; m < Mc; m++) {
            const float* sk = gt_sk + ((b * Mc + m) * Pc + p) * 3;
            float vp = (sk[2] == 1.0f) ? 256.0f : 0.0f;
            float d0 = vp + sk[1] - (float)xi;
            float d1 = vp + sk[2] - (float)yi;
            float d  = sqrtf(d0 * d0 + d1 * d1 + 1e-12f);
            if (d < best) { best = d; bestm = m; }
        }
        g_pid[tid] = bestm;
    }

    if (tid == 192) {
        double sp = 0.0, sl = 0.0;
        for (int j = 0; j < BSc; j++) { sp += (double)spush[j]; sl += (double)spull[j]; }
        g_pushpull[0] = sp;
        g_pushpull[1] = sl;
    }
}

// ============================================================
// Kernel 3: softmax partials — load each element ONCE, compute all 10 k
// grid (SG, Pc, BSc) = 1088 blocks; 30 partial sums per block
// ============================================================
__global__ void __launch_bounds__(256) softpart_kernel(const float* __restrict__ preds) {
    int g  = blockIdx.x;
    int p  = blockIdx.y;
    int bs = blockIdx.z;
    int tid = threadIdx.x;
    const float4* __restrict__ hm4 =
        (const float4*)(preds + ((size_t)bs * Cc + p) * HWc + g * SCHUNK);
    const float4* __restrict__ tg4 = hm4 + (Pc * HWc / 4);

    float tv[Kc];
#pragma unroll
    for (int k = 0; k < Kc; k++) tv[k] = g_tv[bs * Kc + k];

    float se[Kc], sx[Kc], sy[Kc];
#pragma unroll
    for (int k = 0; k < Kc; k++) { se[k] = 0.0f; sx[k] = 0.0f; sy[k] = 0.0f; }

    const float C1 = 4.328085122666891f;    // 3 * log2(e)
    const float C2 = 18.033688011112047f;   // 12.5 * log2(e)

#pragma unroll
    for (int j = 0; j < 2; j++) {
        int idx4 = tid + 256 * j;
        float4 h = hm4[idx4];
        float4 t = tg4[idx4];
        int e0 = g * SCHUNK + 4 * idx4;
        float hs[4] = {h.x, h.y, h.z, h.w};
        float ts[4] = {t.x, t.y, t.z, t.w};
#pragma unroll
        for (int c = 0; c < 4; c++) {
            float Ah = C1 * hs[c];
            float xf = (float)((e0 + c) >> 7);
            float yf = (float)((e0 + c) & 127);
#pragma unroll
            for (int k = 0; k < Kc; k++) {
                float d = ts[c] - tv[k];
                float l = fmaf(d * (-C2), d, Ah);
                float e = exp2f(l);
                se[k] += e;
                sx[k] = fmaf(e, xf, sx[k]);
                sy[k] = fmaf(e, yf, sy[k]);
            }
        }
    }

    // warp reduce 30 accumulators
#pragma unroll
    for (int o = 16; o > 0; o >>= 1) {
#pragma unroll
        for (int k = 0; k < Kc; k++) {
            se[k] += __shfl_xor_sync(0xffffffffu, se[k], o);
            sx[k] += __shfl_xor_sync(0xffffffffu, sx[k], o);
            sy[k] += __shfl_xor_sync(0xffffffffu, sy[k], o);
        }
    }
    __shared__ float swarp[8][30];
    int w = tid >> 5;
    if ((tid & 31) == 0) {
#pragma unroll
        for (int k = 0; k < Kc; k++) {
            swarp[w][k]      = se[k];
            swarp[w][10 + k] = sx[k];
            swarp[w][20 + k] = sy[k];
        }
    }
    __syncthreads();
    if (tid < 30) {
        float s = 0.0f;
#pragma unroll
        for (int ww = 0; ww < 8; ww++) s += swarp[ww][tid];
        g_spart[(((size_t)bs * Pc + p) * SG + g) * 30 + tid] = s;
    }
}

// ============================================================
// Kernel 4: skeleton coords + Huber + deterministic combine
// ============================================================
__global__ void final_kernel(const float* __restrict__ gt_sk, float* __restrict__ out) {
    int tid = threadIdx.x;
    double acc = 0.0;
    for (int t = tid; t < BSc * Kc * Pc; t += 256) {
        int p   = t % Pc;
        int bsk = t / Pc;
        int bs  = bsk / Kc;
        int k   = bsk % Kc;
        int b   = bs >> 1;
        float se = 0.0f, sx = 0.0f, sy = 0.0f;
        int base = ((bs * Pc + p) * SG) * 30;
#pragma unroll
        for (int g = 0; g < SG; g++) {
            se += g_spart[base + g * 30 + k];
            sx += g_spart[base + g * 30 + 10 + k];
            sy += g_spart[base + g * 30 + 20 + k];
        }
        float inv = 1.0f / se;
        float px = sx * inv, py = sy * inv;
        int pid = g_pid[bsk];
        const float* sk = gt_sk + ((b * Mc + pid) * Pc + p) * 3;
        float ex = sk[0] - px;
        float ey = sk[1] - py;
        float err = sqrtf(ex * ex + ey * ey + 1e-12f) * ((sk[2] > 0.0f) ? 1.0f : 0.0f);
        float a = fabsf(err);
        float hub = (a < 0.1f) ? (err * err) : (0.1f * (a - 0.05f));
        acc += (double)hub;
    }
    // parallel det-partial sum (deterministic fixed pattern)
    double dacc = 0.0;
    for (int j = tid; j < BSc * NCH; j += 256) dacc += g_det_part[j];

    __shared__ double sred[256];
    __shared__ double sdet[256];
    sred[tid] = acc;
    sdet[tid] = dacc;
    __syncthreads();
    for (int o = 128; o > 0; o >>= 1) {
        if (tid < o) { sred[tid] += sred[tid + o]; sdet[tid] += sdet[tid + o]; }
        __syncthreads();
    }
    if (tid == 0) {
        double det = sdet[0] / (double)DET_N;
        double total = g_pushpull[0] / 8.0
                     + g_pushpull[1] / 8.0
                     + det
                     + 10.0 * sred[0] / (double)(BSc * Kc * Pc);
        out[0] = (float)total;
    }
}

// ============================================================
extern "C" void kernel_launch(void* const* d_in, const int* in_sizes, int n_in,
                              void* d_out, int out_size) {
    const float* preds       = (const float*)d_in[0];
    const float* gt_masks    = (const float*)d_in[1];
    const float* gt_heatmaps = (const float*)d_in[2];
    const float* gt_sk       = (const float*)d_in[3];
    const int*   gt_kp       = (const int*)d_in[4];

    scan_kernel<<<dim3(NCH, BSc), 256>>>(preds, gt_masks, gt_heatmaps);
    aux_kernel<<<1, 256>>>(preds, gt_sk, gt_kp);
    softpart_kernel<<<dim3(SG, Pc, BSc), 256>>>(preds);
    final_kernel<<<1, 256>>>(gt_sk, (float*)d_out);
}

// round 4
// speedup vs baseline: 9.3341x; 1.2809x over previous
#include <cuda_runtime.h>
#include <math.h>

#define Bc 4
#define Sc 2
#define Pc 17
#define Hc 128
#define Wc 128
#define Mc 8
#define Kc 10
#define Cc 34          // (1+TAG)*P
#define HWc 16384
#define PHWc 278528
#define BSc 8
#define DET_N (Bc*Sc*Pc*HWc)
#define NCH 34
#define CHUNK 8192     // NCH*CHUNK == PHWc
#define SG 8           // softmax chunks per plane
#define SCHUNK 2048    // HWc / SG
#define NITEM (BSc*Kc*Pc)   // 1360
#define SKBLK 6

// ---------------- scratch (device globals) ----------------
__device__ double g_det_part[BSc*NCH];
__device__ float  g_cand_v[BSc*NCH*Kc];
__device__ int    g_cand_i[BSc*NCH*Kc];
__device__ int    g_topi[BSc*Kc];
__device__ float  g_tv[BSc*Kc];
__device__ int    g_pid[BSc*Kc];
__device__ float  g_spart[BSc*Pc*SG*30];
__device__ double g_skelpart[SKBLK];
__device__ double g_pushpull[2];

#define EINV 0.36787944117144233f

// branchless register-resident top-10 insertion
__device__ __forceinline__ void insert10(float val, int idx, float* v, int* ix) {
    if (val <= v[Kc - 1]) return;
#pragma unroll
    for (int k = Kc - 1; k > 0; k--) {
        bool shift = val > v[k - 1];
        bool place = val > v[k];
        float nv = shift ? v[k - 1] : (place ? val : v[k]);
        int   ni = shift ? ix[k - 1] : (place ? idx : ix[k]);
        v[k] = nv; ix[k] = ni;
    }
    if (val > v[0]) { v[0] = val; ix[0] = idx; }
}

// ============================================================
// Kernel 1: fused det-BCE partial + per-chunk top-10 candidates
// grid (NCH, BSc); each block = half a p-plane (8192 elems)
// ============================================================
__global__ void __launch_bounds__(256) scan_kernel(const float* __restrict__ preds,
                                                   const float* __restrict__ gt_masks,
                                                   const float* __restrict__ gt_heatmaps) {
    int ch = blockIdx.x;            // 0..33 : p = ch>>1, half = ch&1
    int bs = blockIdx.y;            // 0..7
    int tid = threadIdx.x;
    int p    = ch >> 1;
    int hw0  = (ch & 1) * CHUNK;
    int b    = bs >> 1;

    const float4* __restrict__ hm4 = (const float4*)(preds + ((size_t)bs * Cc + p) * HWc + hw0);
    const float4* __restrict__ gh4 = (const float4*)(gt_heatmaps + ((size_t)(b * Pc + p)) * HWc + hw0);
    const float4* __restrict__ mk4 = (const float4*)(gt_masks + (size_t)b * HWc + hw0);
    int i0 = ch * CHUNK;

    float v[Kc]; int ix[Kc];
#pragma unroll
    for (int k = 0; k < Kc; k++) { v[k] = -3.0e38f; ix[k] = -1; }
    float facc = 0.0f;

#pragma unroll
    for (int j = 0; j < 8; j++) {
        int idx4 = tid + 256 * j;
        float4 f = hm4[idx4];
        float4 g = gh4[idx4];
        float4 m = mk4[idx4];
        int e = i0 + 4 * idx4;
        insert10(f.x, e + 0, v, ix);
        insert10(f.y, e + 1, v, ix);
        insert10(f.z, e + 2, v, ix);
        insert10(f.w, e + 3, v, ix);
        float hs[4] = {f.x, f.y, f.z, f.w};
        float gs[4] = {g.x, g.y, g.z, g.w};
        float ms[4] = {m.x, m.y, m.z, m.w};
#pragma unroll
        for (int c = 0; c < 4; c++) {
            float prob = __fdividef(1.0f, 1.0f + __expf(-hs[c]));
            float x = prob * ms[c];
            if (gs[c] > EINV) {
                facc += -10.0f * fmaxf(__logf(x), -100.0f);
            } else if (gs[c] < EINV) {
                facc += -0.5f * fmaxf(__logf(1.0f - x), -100.0f);
            }
        }
    }

    // det block reduction (double from here)
    __shared__ double dred[256];
    dred[tid] = (double)facc;
    __syncthreads();
    for (int o = 128; o > 0; o >>= 1) {
        if (tid < o) dred[tid] += dred[tid + o];
        __syncthreads();
    }
    if (tid == 0) g_det_part[bs * NCH + ch] = dred[0];

    // top-10 selection over 2560 thread-candidates
    __shared__ float sv[256 * Kc];
    __shared__ int   si[256 * Kc];
#pragma unroll
    for (int k = 0; k < Kc; k++) {
        sv[tid * Kc + k] = v[k];
        si[tid * Kc + k] = ix[k];
    }
    __syncthreads();
    __shared__ float rv[256];
    __shared__ int   ri[256];
    for (int sel = 0; sel < Kc; sel++) {
        float bm = -3.2e38f; int bi = 0;
        for (int j = tid; j < 256 * Kc; j += 256)
            if (sv[j] > bm) { bm = sv[j]; bi = j; }
        rv[tid] = bm; ri[tid] = bi;
        __syncthreads();
        for (int o = 128; o > 0; o >>= 1) {
            if (tid < o && rv[tid + o] > rv[tid]) {
                rv[tid] = rv[tid + o];
                ri[tid] = ri[tid + o];
            }
            __syncthreads();
        }
        if (tid == 0) {
            int slot = (bs * NCH + ch) * Kc + sel;
            g_cand_v[slot] = rv[0];
            g_cand_i[slot] = si[ri[0]];
            sv[ri[0]] = -3.3e38f;
        }
        __syncthreads();
    }
}

// ============================================================
// Kernel 2: top-K merge + tv + person_ids + tag push/pull
// ============================================================
__global__ void aux_kernel(const float* __restrict__ preds,
                           const float* __restrict__ gt_sk,
                           const int* __restrict__ gt_kp) {
    int tid = threadIdx.x;
    int w = tid >> 5;
    int lane = tid & 31;
    __shared__ float spush[BSc], spull[BSc];

    // merge 340 candidates -> top-10 per bs (warps 0..7)
    if (w < BSc) {
        int bs = w;
        float cv[11]; int ci[11];
#pragma unroll
        for (int j = 0; j < 11; j++) {
            int c = lane * 11 + j;
            if (c < NCH * Kc) {
                cv[j] = g_cand_v[bs * NCH * Kc + c];
                ci[j] = g_cand_i[bs * NCH * Kc + c];
            } else { cv[j] = -3.3e38f; ci[j] = -1; }
        }
        for (int sel = 0; sel < Kc; sel++) {
            float bv = -3.35e38f; int bj = 0;
#pragma unroll
            for (int j = 0; j < 11; j++)
                if (cv[j] > bv) { bv = cv[j]; bj = j; }
            int bidx = ci[bj];
            int wown = lane, wslot = bj;
#pragma unroll
            for (int o = 16; o > 0; o >>= 1) {
                float ov = __shfl_xor_sync(0xffffffffu, bv, o);
                int   oi = __shfl_xor_sync(0xffffffffu, bidx, o);
                int   oo = __shfl_xor_sync(0xffffffffu, wown, o);
                int   os = __shfl_xor_sync(0xffffffffu, wslot, o);
                if (ov > bv) { bv = ov; bidx = oi; wown = oo; wslot = os; }
            }
            if (lane == wown) cv[wslot] = -3.3e38f;
            if (lane == 0) g_topi[bs * Kc + sel] = bidx;
        }
    }

    // tag push/pull (threads 128..135, one per bs)
    if (tid >= 128 && tid < 128 + BSc) {
        int bs = tid - 128;
        int b  = bs / Sc;
        const float* tb = preds + ((size_t)bs * Cc + Pc) * HWc;
        float mean[Mc], validf[Mc], pullpp[Mc];
        float num = 0.0f;
        for (int m = 0; m < Mc; m++) {
            float gv[Pc], vv[Pc];
            float cnt = 0.0f, sum = 0.0f;
#pragma unroll
            for (int p = 0; p < Pc; p++) {
                const int* kp = gt_kp + (((b * Mc + m) * Pc + p) * 2);
                int idx = kp[0];
                float vis = (kp[1] > 0) ? 1.0f : 0.0f;
                float g = tb[idx];
                gv[p] = g; vv[p] = vis;
                cnt += vis; sum += vis * g;
            }
            float valid = (cnt > 0.0f) ? 1.0f : 0.0f;
            float safe  = fmaxf(cnt, 1.0f);
            float mt = sum / safe;
            mean[m] = mt; validf[m] = valid;
            float pp = 0.0f;
#pragma unroll
            for (int p = 0; p < Pc; p++) {
                float d = gv[p] - mt;
                pp += d * d * vv[p];
            }
            pullpp[m] = pp / safe;
            num += valid;
        }
        float pull = 0.0f;
        for (int m = 0; m < Mc; m++) pull += pullpp[m] * validf[m];
        pull /= (num + 1e-6f);
        float pmsum = 0.0f;
        for (int i2 = 0; i2 < Mc; i2++)
            for (int j = 0; j < Mc; j++) {
                float d = mean[i2] - mean[j];
                pmsum += expf(-d * d) * validf[i2] * validf[j];
            }
        float push = (pmsum - num) / ((num - 1.0f) * num + 1e-6f) * 0.5f;
        spush[bs] = push; spull[bs] = pull;
    }
    __syncthreads();

    // tv & person_ids (needs merged g_topi)
    if (tid < BSc * Kc) {
        int bs = tid / Kc;
        int b  = bs / Sc;
        int i  = g_topi[tid];
        int p  = i / HWc;
        int hw = i % HWc;
        int xi = hw / Wc;
        int yi = hw % Wc;
        g_tv[tid] = preds[((size_t)bs * Cc + Pc) * HWc + i];
        float best = 3.4e38f; int bestm = 0;
        for (int m = 0; m < Mc; m++) {
            const float* sk = gt_sk + ((b * Mc + m) * Pc + p) * 3;
            float vp = (sk[2] == 1.0f) ? 256.0f : 0.0f;
            float d0 = vp + sk[1] - (float)xi;
            float d1 = vp + sk[2] - (float)yi;
            float d  = sqrtf(d0 * d0 + d1 * d1 + 1e-12f);
            if (d < best) { best = d; bestm = m; }
        }
        g_pid[tid] = bestm;
    }

    if (tid == 192) {
        double sp = 0.0, sl = 0.0;
        for (int j = 0; j < BSc; j++) { sp += (double)spush[j]; sl += (double)spull[j]; }
        g_pushpull[0] = sp;
        g_pushpull[1] = sl;
    }
}

// ============================================================
// Kernel 3: softmax partials — anchored exponent, each element read once
// grid (SG, Pc, BSc) = 1088 blocks; 30 partial sums per block
// anchor L = C1 * max(hm over plane) (from scan's per-chunk top-1);
// cancels in px = sx/se, prevents subnormal flush for far tags.
// ============================================================
__global__ void __launch_bounds__(256) softpart_kernel(const float* __restrict__ preds) {
    int g  = blockIdx.x;
    int p  = blockIdx.y;
    int bs = blockIdx.z;
    int tid = threadIdx.x;
    const float4* __restrict__ hm4 =
        (const float4*)(preds + ((size_t)bs * Cc + p) * HWc + g * SCHUNK);
    const float4* __restrict__ tg4 = hm4 + (Pc * HWc / 4);

    const float C1 = 4.328085122666891f;    // 3 * log2(e)
    const float C2 = 18.033688011112047f;   // 12.5 * log2(e)
    // plane max of hm (scan chunk ch=2p and 2p+1, sel=0)
    float hmax = fmaxf(g_cand_v[(bs * NCH + 2 * p) * Kc],
                       g_cand_v[(bs * NCH + 2 * p + 1) * Kc]);
    float L = C1 * hmax;

    float tv[Kc];
#pragma unroll
    for (int k = 0; k < Kc; k++) tv[k] = g_tv[bs * Kc + k];

    float se[Kc], sx[Kc], sy[Kc];
#pragma unroll
    for (int k = 0; k < Kc; k++) { se[k] = 0.0f; sx[k] = 0.0f; sy[k] = 0.0f; }

#pragma unroll
    for (int j = 0; j < 2; j++) {
        int idx4 = tid + 256 * j;
        float4 h = hm4[idx4];
        float4 t = tg4[idx4];
        int e0 = g * SCHUNK + 4 * idx4;
        float hs[4] = {h.x, h.y, h.z, h.w};
        float ts[4] = {t.x, t.y, t.z, t.w};
#pragma unroll
        for (int c = 0; c < 4; c++) {
            float base = fmaf(C1, hs[c], -L);
            float xf = (float)((e0 + c) >> 7);
            float yf = (float)((e0 + c) & 127);
#pragma unroll
            for (int k = 0; k < Kc; k++) {
                float d = ts[c] - tv[k];
                float l = fmaf(d * (-C2), d, base);
                float e = exp2f(l);
                se[k] += e;
                sx[k] = fmaf(e, xf, sx[k]);
                sy[k] = fmaf(e, yf, sy[k]);
            }
        }
    }

#pragma unroll
    for (int o = 16; o > 0; o >>= 1) {
#pragma unroll
        for (int k = 0; k < Kc; k++) {
            se[k] += __shfl_xor_sync(0xffffffffu, se[k], o);
            sx[k] += __shfl_xor_sync(0xffffffffu, sx[k], o);
            sy[k] += __shfl_xor_sync(0xffffffffu, sy[k], o);
        }
    }
    __shared__ float swarp[8][30];
    int w = tid >> 5;
    if ((tid & 31) == 0) {
#pragma unroll
        for (int k = 0; k < Kc; k++) {
            swarp[w][k]      = se[k];
            swarp[w][10 + k] = sx[k];
            swarp[w][20 + k] = sy[k];
        }
    }
    __syncthreads();
    if (tid < 30) {
        float s = 0.0f;
#pragma unroll
        for (int ww = 0; ww < 8; ww++) s += swarp[ww][tid];
        g_spart[(((size_t)bs * Pc + p) * SG + g) * 30 + tid] = s;
    }
}

// ============================================================
// Kernel 4: skeleton coords + Huber, 6 blocks (parallel, MLP-rich)
// ============================================================
__global__ void __launch_bounds__(256) skel_kernel(const float* __restrict__ gt_sk) {
    int tid = threadIdx.x;
    int t = blockIdx.x * 256 + tid;
    float hub = 0.0f;
    if (t < NITEM) {
        int p   = t % Pc;
        int bsk = t / Pc;
        int bs  = bsk / Kc;
        int k   = bsk % Kc;
        int b   = bs >> 1;
        float se = 0.0f, sx = 0.0f, sy = 0.0f;
        int base = ((bs * Pc + p) * SG) * 30;
#pragma unroll
        for (int g = 0; g < SG; g++) {
            se += g_spart[base + g * 30 + k];
            sx += g_spart[base + g * 30 + 10 + k];
            sy += g_spart[base + g * 30 + 20 + k];
        }
        float inv = 1.0f / se;
        float px = sx * inv, py = sy * inv;
        int pid = g_pid[bsk];
        const float* sk = gt_sk + ((b * Mc + pid) * Pc + p) * 3;
        float ex = sk[0] - px;
        float ey = sk[1] - py;
        float err = sqrtf(ex * ex + ey * ey + 1e-12f) * ((sk[2] > 0.0f) ? 1.0f : 0.0f);
        float a = fabsf(err);
        hub = (a < 0.1f) ? (err * err) : (0.1f * (a - 0.05f));
    }
    __shared__ double sred[256];
    sred[tid] = (double)hub;
    __syncthreads();
    for (int o = 128; o > 0; o >>= 1) {
        if (tid < o) sred[tid] += sred[tid + o];
        __syncthreads();
    }
    if (tid == 0) g_skelpart[blockIdx.x] = sred[0];
}

// ============================================================
// Kernel 5: deterministic final combine (tiny)
// ============================================================
__global__ void final_kernel(float* __restrict__ out) {
    int tid = threadIdx.x;
    double dacc = 0.0;
    for (int j = tid; j < BSc * NCH; j += 256) dacc += g_det_part[j];
    __shared__ double sdet[256];
    sdet[tid] = dacc;
    __syncthreads();
    for (int o = 128; o > 0; o >>= 1) {
        if (tid < o) sdet[tid] += sdet[tid + o];
        __syncthreads();
    }
    if (tid == 0) {
        double sk = 0.0;
        for (int j = 0; j < SKBLK; j++) sk += g_skelpart[j];
        double det = sdet[0] / (double)DET_N;
        double total = g_pushpull[0] / 8.0
                     + g_pushpull[1] / 8.0
                     + det
                     + 10.0 * sk / (double)NITEM;
        out[0] = (float)total;
    }
}

// ============================================================
extern "C" void kernel_launch(void* const* d_in, const int* in_sizes, int n_in,
                              void* d_out, int out_size) {
    const float* preds       = (const float*)d_in[0];
    const float* gt_masks    = (const float*)d_in[1];
    const float* gt_heatmaps = (const float*)d_in[2];
    const float* gt_sk       = (const float*)d_in[3];
    const int*   gt_kp       = (const int*)d_in[4];

    scan_kernel<<<dim3(NCH, BSc), 256>>>(preds, gt_masks, gt_heatmaps);
    aux_kernel<<<1, 256>>>(preds, gt_sk, gt_kp);
    softpart_kernel<<<dim3(SG, Pc, BSc), 256>>>(preds);
    skel_kernel<<<SKBLK, 256>>>(gt_sk);
    final_kernel<<<1, 256>>>((float*)d_out);
}

// round 5
// speedup vs baseline: 11.0968x; 1.1888x over previous
#include <cuda_runtime.h>
#include <math.h>

#define Bc 4
#define Sc 2
#define Pc 17
#define Hc 128
#define Wc 128
#define Mc 8
#define Kc 10
#define Cc 34          // (1+TAG)*P
#define HWc 16384
#define PHWc 278528
#define BSc 8
#define DET_N (Bc*Sc*Pc*HWc)
#define NCH 34
#define CHUNK 8192     // NCH*CHUNK == PHWc
#define NITEM (BSc*Kc*Pc)   // 1360

// ---------------- scratch (device globals) ----------------
__device__ double g_det_part[BSc*NCH];
__device__ float  g_cand_v[BSc*NCH*Kc];
__device__ int    g_cand_i[BSc*NCH*Kc];
__device__ int    g_topi[BSc*Kc];
__device__ float  g_tv[BSc*Kc];
__device__ int    g_pid[BSc*Kc];
__device__ double g_hubpart[BSc*Pc];
__device__ double g_pushpull[2];

#define EINV 0.36787944117144233f

// branchless register-resident top-10 insertion
__device__ __forceinline__ void insert10(float val, int idx, float* v, int* ix) {
    if (val <= v[Kc - 1]) return;
#pragma unroll
    for (int k = Kc - 1; k > 0; k--) {
        bool shift = val > v[k - 1];
        bool place = val > v[k];
        float nv = shift ? v[k - 1] : (place ? val : v[k]);
        int   ni = shift ? ix[k - 1] : (place ? idx : ix[k]);
        v[k] = nv; ix[k] = ni;
    }
    if (val > v[0]) { v[0] = val; ix[0] = idx; }
}

// ============================================================
// Kernel 1: fused det-BCE partial + per-chunk top-10 candidates
// grid (NCH, BSc); each block = half a p-plane (8192 elems)
// ============================================================
__global__ void __launch_bounds__(256) scan_kernel(const float* __restrict__ preds,
                                                   const float* __restrict__ gt_masks,
                                                   const float* __restrict__ gt_heatmaps) {
    int ch = blockIdx.x;            // 0..33 : p = ch>>1, half = ch&1
    int bs = blockIdx.y;            // 0..7
    int tid = threadIdx.x;
    int p    = ch >> 1;
    int hw0  = (ch & 1) * CHUNK;
    int b    = bs >> 1;

    const float4* __restrict__ hm4 = (const float4*)(preds + ((size_t)bs * Cc + p) * HWc + hw0);
    const float4* __restrict__ gh4 = (const float4*)(gt_heatmaps + ((size_t)(b * Pc + p)) * HWc + hw0);
    const float4* __restrict__ mk4 = (const float4*)(gt_masks + (size_t)b * HWc + hw0);
    int i0 = ch * CHUNK;

    float v[Kc]; int ix[Kc];
#pragma unroll
    for (int k = 0; k < Kc; k++) { v[k] = -3.0e38f; ix[k] = -1; }
    float facc = 0.0f;

#pragma unroll
    for (int j = 0; j < 8; j++) {
        int idx4 = tid + 256 * j;
        float4 f = hm4[idx4];
        float4 g = gh4[idx4];
        float4 m = mk4[idx4];
        int e = i0 + 4 * idx4;
        insert10(f.x, e + 0, v, ix);
        insert10(f.y, e + 1, v, ix);
        insert10(f.z, e + 2, v, ix);
        insert10(f.w, e + 3, v, ix);
        float hs[4] = {f.x, f.y, f.z, f.w};
        float gs[4] = {g.x, g.y, g.z, g.w};
        float ms[4] = {m.x, m.y, m.z, m.w};
#pragma unroll
        for (int c = 0; c < 4; c++) {
            float prob = __fdividef(1.0f, 1.0f + __expf(-hs[c]));
            float x = prob * ms[c];
            if (gs[c] > EINV) {
                facc += -10.0f * fmaxf(__logf(x), -100.0f);
            } else if (gs[c] < EINV) {
                facc += -0.5f * fmaxf(__logf(1.0f - x), -100.0f);
            }
        }
    }

    // det block reduction (double from here)
    __shared__ double dred[256];
    dred[tid] = (double)facc;
    __syncthreads();
    for (int o = 128; o > 0; o >>= 1) {
        if (tid < o) dred[tid] += dred[tid + o];
        __syncthreads();
    }
    if (tid == 0) g_det_part[bs * NCH + ch] = dred[0];

    // top-10 selection over 2560 thread-candidates
    __shared__ float sv[256 * Kc];
    __shared__ int   si[256 * Kc];
#pragma unroll
    for (int k = 0; k < Kc; k++) {
        sv[tid * Kc + k] = v[k];
        si[tid * Kc + k] = ix[k];
    }
    __syncthreads();
    __shared__ float rv[256];
    __shared__ int   ri[256];
    for (int sel = 0; sel < Kc; sel++) {
        float bm = -3.2e38f; int bi = 0;
        for (int j = tid; j < 256 * Kc; j += 256)
            if (sv[j] > bm) { bm = sv[j]; bi = j; }
        rv[tid] = bm; ri[tid] = bi;
        __syncthreads();
        for (int o = 128; o > 0; o >>= 1) {
            if (tid < o && rv[tid + o] > rv[tid]) {
                rv[tid] = rv[tid + o];
                ri[tid] = ri[tid + o];
            }
            __syncthreads();
        }
        if (tid == 0) {
            int slot = (bs * NCH + ch) * Kc + sel;
            g_cand_v[slot] = rv[0];
            g_cand_i[slot] = si[ri[0]];
            sv[ri[0]] = -3.3e38f;
        }
        __syncthreads();
    }
}

// ============================================================
// Kernel 2: top-K merge (warps 0-7) + tag push/pull (warps 8-15, 1 warp/bs)
//           + tv & person_ids (phase B)
// ============================================================
__global__ void __launch_bounds__(512) aux_kernel(const float* __restrict__ preds,
                                                  const float* __restrict__ gt_sk,
                                                  const int* __restrict__ gt_kp) {
    int tid = threadIdx.x;
    int w = tid >> 5;
    int lane = tid & 31;
    __shared__ float spush[BSc], spull[BSc];

    if (w < BSc) {
        // ---- merge 340 candidates -> top-10 per bs ----
        int bs = w;
        float cv[11]; int ci[11];
#pragma unroll
        for (int j = 0; j < 11; j++) {
            int c = lane * 11 + j;
            if (c < NCH * Kc) {
                cv[j] = g_cand_v[bs * NCH * Kc + c];
                ci[j] = g_cand_i[bs * NCH * Kc + c];
            } else { cv[j] = -3.3e38f; ci[j] = -1; }
        }
        for (int sel = 0; sel < Kc; sel++) {
            float bv = -3.35e38f; int bj = 0;
#pragma unroll
            for (int j = 0; j < 11; j++)
                if (cv[j] > bv) { bv = cv[j]; bj = j; }
            int bidx = ci[bj];
            int wown = lane, wslot = bj;
#pragma unroll
            for (int o = 16; o > 0; o >>= 1) {
                float ov = __shfl_xor_sync(0xffffffffu, bv, o);
                int   oi = __shfl_xor_sync(0xffffffffu, bidx, o);
                int   oo = __shfl_xor_sync(0xffffffffu, wown, o);
                int   os = __shfl_xor_sync(0xffffffffu, wslot, o);
                if (ov > bv) { bv = ov; bidx = oi; wown = oo; wslot = os; }
            }
            if (lane == wown) cv[wslot] = -3.3e38f;
            if (lane == 0) g_topi[bs * Kc + sel] = bidx;
        }
    } else {
        // ---- push/pull, one warp per bs; lane = m*4 + q ----
        int bs = w - BSc;
        int b  = bs / Sc;
        int m  = lane >> 2;
        int q  = lane & 3;
        int np = (q == 0) ? 5 : 4;           // p = q + 4*i
        const float* tb = preds + ((size_t)bs * Cc + Pc) * HWc;
        const int* kpb = gt_kp + ((b * Mc + m) * Pc) * 2;

        float gv[5], vv[5];
        float cnt = 0.0f, sum = 0.0f;
#pragma unroll
        for (int i = 0; i < 5; i++) {
            gv[i] = 0.0f; vv[i] = 0.0f;
            if (i < np) {
                int pp2 = q + 4 * i;
                int idx  = kpb[2 * pp2];
                float vis = (kpb[2 * pp2 + 1] > 0) ? 1.0f : 0.0f;
                float g = tb[idx];
                gv[i] = g; vv[i] = vis;
                cnt += vis; sum += vis * g;
            }
        }
        // reduce over q (4 lanes of same m)
        cnt += __shfl_xor_sync(0xffffffffu, cnt, 1);
        cnt += __shfl_xor_sync(0xffffffffu, cnt, 2);
        sum += __shfl_xor_sync(0xffffffffu, sum, 1);
        sum += __shfl_xor_sync(0xffffffffu, sum, 2);
        float valid = (cnt > 0.0f) ? 1.0f : 0.0f;
        float safe  = fmaxf(cnt, 1.0f);
        float mean  = sum / safe;
        float pp = 0.0f;
#pragma unroll
        for (int i = 0; i < 5; i++) {
            float d = gv[i] - mean;
            pp += d * d * vv[i];
        }
        pp += __shfl_xor_sync(0xffffffffu, pp, 1);
        pp += __shfl_xor_sync(0xffffffffu, pp, 2);
        float pull_m = (pp / safe) * valid;
        // sums across m (butterfly over strides 4,8,16)
        float num = valid, pullsum = pull_m;
#pragma unroll
        for (int o = 4; o <= 16; o <<= 1) {
            num     += __shfl_xor_sync(0xffffffffu, num, o);
            pullsum += __shfl_xor_sync(0xffffffffu, pullsum, o);
        }
        // push: each lane handles j = q and q+4
        float rowsum = 0.0f;
#pragma unroll
        for (int jj = 0; jj < 2; jj++) {
            int j = q + 4 * jj;
            float mj = __shfl_sync(0xffffffffu, mean, j * 4);
            float vj = __shfl_sync(0xffffffffu, valid, j * 4);
            float d = mean - mj;
            rowsum += expf(-d * d) * valid * vj;
        }
        rowsum += __shfl_xor_sync(0xffffffffu, rowsum, 1);
        rowsum += __shfl_xor_sync(0xffffffffu, rowsum, 2);
        float pmsum = rowsum;
#pragma unroll
        for (int o = 4; o <= 16; o <<= 1)
            pmsum += __shfl_xor_sync(0xffffffffu, pmsum, o);
        if (lane == 0) {
            spush[bs] = (pmsum - num) / ((num - 1.0f) * num + 1e-6f) * 0.5f;
            spull[bs] = pullsum / (num + 1e-6f);
        }
    }
    __syncthreads();

    // ---- phase B: tv & person_ids (needs merged g_topi) ----
    if (tid < BSc * Kc) {
        int bs = tid / Kc;
        int b  = bs / Sc;
        int i  = g_topi[tid];
        int p  = i / HWc;
        int hw = i % HWc;
        int xi = hw / Wc;
        int yi = hw % Wc;
        g_tv[tid] = preds[((size_t)bs * Cc + Pc) * HWc + i];
        float best = 3.4e38f; int bestm = 0;
        for (int m = 0; m < Mc; m++) {
            const float* sk = gt_sk + ((b * Mc + m) * Pc + p) * 3;
            float vp = (sk[2] == 1.0f) ? 256.0f : 0.0f;
            float d0 = vp + sk[1] - (float)xi;
            float d1 = vp + sk[2] - (float)yi;
            float d  = sqrtf(d0 * d0 + d1 * d1 + 1e-12f);
            if (d < best) { best = d; bestm = m; }
        }
        g_pid[tid] = bestm;
    }
    if (tid == 511) {
        double sp = 0.0, sl = 0.0;
        for (int j = 0; j < BSc; j++) { sp += (double)spush[j]; sl += (double)spull[j]; }
        g_pushpull[0] = sp;
        g_pushpull[1] = sl;
    }
}

// ============================================================
// Kernel 3: one block per (bs,p) plane — 10-k softmax sums + fused Huber
// 512 threads, anchored exponent, element read once, all 10 k in registers
// ============================================================
__global__ void __launch_bounds__(512) softhub_kernel(const float* __restrict__ preds,
                                                      const float* __restrict__ gt_sk) {
    int p  = blockIdx.x;
    int bs = blockIdx.y;
    int tid = threadIdx.x;
    const float4* __restrict__ hm4 = (const float4*)(preds + ((size_t)bs * Cc + p) * HWc);
    const float4* __restrict__ tg4 = hm4 + (Pc * HWc / 4);

    const float C1 = 4.328085122666891f;    // 3 * log2(e)
    const float C2 = 18.033688011112047f;   // 12.5 * log2(e)
    float hmax = fmaxf(g_cand_v[(bs * NCH + 2 * p) * Kc],
                       g_cand_v[(bs * NCH + 2 * p + 1) * Kc]);
    float L = C1 * hmax;

    float tv[Kc];
#pragma unroll
    for (int k = 0; k < Kc; k++) tv[k] = g_tv[bs * Kc + k];

    float se[Kc], sx[Kc], sy[Kc];
#pragma unroll
    for (int k = 0; k < Kc; k++) { se[k] = 0.0f; sx[k] = 0.0f; sy[k] = 0.0f; }

#pragma unroll 2
    for (int j = 0; j < 8; j++) {
        int idx4 = tid + 512 * j;
        float4 h = hm4[idx4];
        float4 t = tg4[idx4];
        int e0 = 4 * idx4;
        float hs[4] = {h.x, h.y, h.z, h.w};
        float ts[4] = {t.x, t.y, t.z, t.w};
        float xf = (float)(e0 >> 7);          // row constant within float4
        float yb = (float)(e0 & 127);
#pragma unroll
        for (int c = 0; c < 4; c++) {
            float base = fmaf(C1, hs[c], -L);
            float yf = yb + (float)c;
#pragma unroll
            for (int k = 0; k < Kc; k++) {
                float d = ts[c] - tv[k];
                float l = fmaf(d * (-C2), d, base);
                float e = exp2f(l);
                se[k] += e;
                sx[k] = fmaf(e, xf, sx[k]);
                sy[k] = fmaf(e, yf, sy[k]);
            }
        }
    }

#pragma unroll
    for (int o = 16; o > 0; o >>= 1) {
#pragma unroll
        for (int k = 0; k < Kc; k++) {
            se[k] += __shfl_xor_sync(0xffffffffu, se[k], o);
            sx[k] += __shfl_xor_sync(0xffffffffu, sx[k], o);
            sy[k] += __shfl_xor_sync(0xffffffffu, sy[k], o);
        }
    }
    __shared__ float swarp[16][30];
    int w = tid >> 5;
    if ((tid & 31) == 0) {
#pragma unroll
        for (int k = 0; k < Kc; k++) {
            swarp[w][k]      = se[k];
            swarp[w][10 + k] = sx[k];
            swarp[w][20 + k] = sy[k];
        }
    }
    __syncthreads();
    __shared__ float tot[30];
    if (tid < 30) {
        float s = 0.0f;
#pragma unroll
        for (int ww = 0; ww < 16; ww++) s += swarp[ww][tid];
        tot[tid] = s;
    }
    __syncthreads();

    // fused Huber: thread k handles top-k index k
    __shared__ double shub[Kc];
    if (tid < Kc) {
        int k = tid;
        int b = bs >> 1;
        float seT = tot[k], sxT = tot[10 + k], syT = tot[20 + k];
        float inv = 1.0f / seT;
        float px = sxT * inv, py = syT * inv;
        int pid = g_pid[bs * Kc + k];
        const float* sk = gt_sk + ((b * Mc + pid) * Pc + p) * 3;
        float ex = sk[0] - px;
        float ey = sk[1] - py;
        float err = sqrtf(ex * ex + ey * ey + 1e-12f) * ((sk[2] > 0.0f) ? 1.0f : 0.0f);
        float a = fabsf(err);
        shub[k] = (double)((a < 0.1f) ? (err * err) : (0.1f * (a - 0.05f)));
    }
    __syncthreads();
    if (tid == 0) {
        double s = 0.0;
#pragma unroll
        for (int k = 0; k < Kc; k++) s += shub[k];
        g_hubpart[bs * Pc + p] = s;
    }
}

// ============================================================
// Kernel 4: deterministic final combine
// ============================================================
__global__ void __launch_bounds__(256) final_kernel(float* __restrict__ out) {
    int tid = threadIdx.x;
    double dacc = 0.0, hacc = 0.0;
    for (int j = tid; j < BSc * NCH; j += 256) dacc += g_det_part[j];
    for (int j = tid; j < BSc * Pc; j += 256) hacc += g_hubpart[j];
    __shared__ double sdet[256], shub[256];
    sdet[tid] = dacc;
    shub[tid] = hacc;
    __syncthreads();
    for (int o = 128; o > 0; o >>= 1) {
        if (tid < o) { sdet[tid] += sdet[tid + o]; shub[tid] += shub[tid + o]; }
        __syncthreads();
    }
    if (tid == 0) {
        double det = sdet[0] / (double)DET_N;
        double total = g_pushpull[0] / 8.0
                     + g_pushpull[1] / 8.0
                     + det
                     + 10.0 * shub[0] / (double)NITEM;
        out[0] = (float)total;
    }
}

// ============================================================
extern "C" void kernel_launch(void* const* d_in, const int* in_sizes, int n_in,
                              void* d_out, int out_size) {
    const float* preds       = (const float*)d_in[0];
    const float* gt_masks    = (const float*)d_in[1];
    const float* gt_heatmaps = (const float*)d_in[2];
    const float* gt_sk       = (const float*)d_in[3];
    const int*   gt_kp       = (const int*)d_in[4];

    scan_kernel<<<dim3(NCH, BSc), 256>>>(preds, gt_masks, gt_heatmaps);
    aux_kernel<<<1, 512>>>(preds, gt_sk, gt_kp);
    softhub_kernel<<<dim3(Pc, BSc), 512>>>(preds, gt_sk);
    final_kernel<<<1, 256>>>((float*)d_out);
}

// round 6
// speedup vs baseline: 11.1042x; 1.0007x over previous
#include <cuda_runtime.h>
#include <math.h>

#define Bc 4
#define Sc 2
#define Pc 17
#define Hc 128
#define Wc 128
#define Mc 8
#define Kc 10
#define Cc 34          // (1+TAG)*P
#define HWc 16384
#define PHWc 278528
#define BSc 8
#define DET_N (Bc*Sc*Pc*HWc)
#define NCH 34
#define CHUNK 8192     // NCH*CHUNK == PHWc
#define NITEM (BSc*Kc*Pc)   // 1360
#define SCAN_NBLK (NCH*BSc) // 272
#define SOFT_NBLK (Pc*BSc)  // 136

// ---------------- scratch (device globals) ----------------
__device__ double g_det_part[BSc*NCH];
__device__ float  g_cand_v[BSc*NCH*Kc];
__device__ int    g_cand_i[BSc*NCH*Kc];
__device__ int    g_topi[BSc*Kc];
__device__ float  g_tv[BSc*Kc];
__device__ int    g_pid[BSc*Kc];
__device__ double g_hubpart[BSc*Pc];
__device__ double g_pushpull[2];
__device__ double g_dettot;
__device__ int    g_cnt1 = 0;
__device__ int    g_cnt2 = 0;

#define EINV 0.36787944117144233f

// branchless register-resident top-10 insertion
__device__ __forceinline__ void insert10(float val, int idx, float* v, int* ix) {
    if (val <= v[Kc - 1]) return;
#pragma unroll
    for (int k = Kc - 1; k > 0; k--) {
        bool shift = val > v[k - 1];
        bool place = val > v[k];
        float nv = shift ? v[k - 1] : (place ? val : v[k]);
        int   ni = shift ? ix[k - 1] : (place ? idx : ix[k]);
        v[k] = nv; ix[k] = ni;
    }
    if (val > v[0]) { v[0] = val; ix[0] = idx; }
}

// ============================================================
// Kernel 1: det-BCE + per-chunk top-10; LAST block also does
//           top-K merge + push/pull + tv/pid + det total (aux tail)
// grid (NCH, BSc) = 272 blocks, 256 threads
// ============================================================
__global__ void __launch_bounds__(256) scan_kernel(const float* __restrict__ preds,
                                                   const float* __restrict__ gt_masks,
                                                   const float* __restrict__ gt_heatmaps,
                                                   const float* __restrict__ gt_sk,
                                                   const int* __restrict__ gt_kp) {
    int ch = blockIdx.x;            // 0..33 : p = ch>>1, half = ch&1
    int bs = blockIdx.y;            // 0..7
    int tid = threadIdx.x;
    int w = tid >> 5;
    int lane = tid & 31;
    int p    = ch >> 1;
    int hw0  = (ch & 1) * CHUNK;
    int b    = bs >> 1;

    const float4* __restrict__ hm4 = (const float4*)(preds + ((size_t)bs * Cc + p) * HWc + hw0);
    const float4* __restrict__ gh4 = (const float4*)(gt_heatmaps + ((size_t)(b * Pc + p)) * HWc + hw0);
    const float4* __restrict__ mk4 = (const float4*)(gt_masks + (size_t)b * HWc + hw0);
    int i0 = ch * CHUNK;

    float v[Kc]; int ix[Kc];
#pragma unroll
    for (int k = 0; k < Kc; k++) { v[k] = -3.0e38f; ix[k] = -1; }
    float facc = 0.0f;

#pragma unroll
    for (int j = 0; j < 8; j++) {
        int idx4 = tid + 256 * j;
        float4 f = hm4[idx4];
        float4 g = gh4[idx4];
        float4 m = mk4[idx4];
        int e = i0 + 4 * idx4;
        insert10(f.x, e + 0, v, ix);
        insert10(f.y, e + 1, v, ix);
        insert10(f.z, e + 2, v, ix);
        insert10(f.w, e + 3, v, ix);
        float hs[4] = {f.x, f.y, f.z, f.w};
        float gs[4] = {g.x, g.y, g.z, g.w};
        float ms[4] = {m.x, m.y, m.z, m.w};
#pragma unroll
        for (int c = 0; c < 4; c++) {
            float prob = __fdividef(1.0f, 1.0f + __expf(-hs[c]));
            float x = prob * ms[c];
            if (gs[c] > EINV) {
                facc += -10.0f * fmaxf(__logf(x), -100.0f);
            } else if (gs[c] < EINV) {
                facc += -0.5f * fmaxf(__logf(1.0f - x), -100.0f);
            }
        }
    }

    // det block reduction
    __shared__ double dred[256];
    dred[tid] = (double)facc;
    __syncthreads();
    for (int o = 128; o > 0; o >>= 1) {
        if (tid < o) dred[tid] += dred[tid + o];
        __syncthreads();
    }
    if (tid == 0) g_det_part[bs * NCH + ch] = dred[0];

    // ---- top-10 selection: register-resident warp argmax ----
    __shared__ float swv[8];
    __shared__ int   swi[8];
    __shared__ int   swm[8];
    __shared__ int   winsel;    // (winning warp << 16) | meta
    for (int sel = 0; sel < Kc; sel++) {
        float bv = v[0]; int bidx = ix[0]; int bmeta = lane * 16;
#pragma unroll
        for (int j = 1; j < Kc; j++)
            if (v[j] > bv) { bv = v[j]; bidx = ix[j]; bmeta = lane * 16 + j; }
#pragma unroll
        for (int o = 16; o > 0; o >>= 1) {
            float ov = __shfl_xor_sync(0xffffffffu, bv, o);
            int   oi = __shfl_xor_sync(0xffffffffu, bidx, o);
            int   om = __shfl_xor_sync(0xffffffffu, bmeta, o);
            if (ov > bv) { bv = ov; bidx = oi; bmeta = om; }
        }
        if (lane == 0) { swv[w] = bv; swi[w] = bidx; swm[w] = bmeta; }
        __syncthreads();
        if (tid == 0) {
            float bb = swv[0]; int bw = 0;
#pragma unroll
            for (int j = 1; j < 8; j++)
                if (swv[j] > bb) { bb = swv[j]; bw = j; }
            int slot = (bs * NCH + ch) * Kc + sel;
            g_cand_v[slot] = bb;
            g_cand_i[slot] = swi[bw];
            winsel = (bw << 16) | swm[bw];
        }
        __syncthreads();
        int ws = winsel;
        if (w == (ws >> 16) && lane == ((ws >> 4) & 31)) {
            int slot = ws & 15;
#pragma unroll
            for (int j = 0; j < Kc; j++)
                if (j == slot) v[j] = -3.1e38f;
        }
        __syncthreads();
    }

    // ================= last-block aux tail =================
    __threadfence();
    __shared__ int isLast;
    if (tid == 0) {
        int c = atomicAdd(&g_cnt1, 1);
        isLast = (c == SCAN_NBLK - 1) ? 1 : 0;
    }
    __syncthreads();
    if (!isLast) return;
    __threadfence();

    __shared__ float spush[BSc], spull[BSc];

    // --- merge 340 candidates -> top-10 per bs (warp w handles bs=w) ---
    {
        int mbs = w;
        float cv[11]; int ci[11];
#pragma unroll
        for (int j = 0; j < 11; j++) {
            int c = lane * 11 + j;
            if (c < NCH * Kc) {
                cv[j] = g_cand_v[mbs * NCH * Kc + c];
                ci[j] = g_cand_i[mbs * NCH * Kc + c];
            } else { cv[j] = -3.3e38f; ci[j] = -1; }
        }
        for (int sel = 0; sel < Kc; sel++) {
            float bv = -3.35e38f; int bj = 0;
#pragma unroll
            for (int j = 0; j < 11; j++)
                if (cv[j] > bv) { bv = cv[j]; bj = j; }
            int bidx = ci[bj];
            int wown = lane, wslot = bj;
#pragma unroll
            for (int o = 16; o > 0; o >>= 1) {
                float ov = __shfl_xor_sync(0xffffffffu, bv, o);
                int   oi = __shfl_xor_sync(0xffffffffu, bidx, o);
                int   oo = __shfl_xor_sync(0xffffffffu, wown, o);
                int   os = __shfl_xor_sync(0xffffffffu, wslot, o);
                if (ov > bv) { bv = ov; bidx = oi; wown = oo; wslot = os; }
            }
            if (lane == wown) cv[wslot] = -3.3e38f;
            if (lane == 0) g_topi[mbs * Kc + sel] = bidx;
        }
    }
    __syncthreads();

    // --- push/pull (warp w handles bs=w; lane = m*4 + q) ---
    {
        int mbs = w;
        int mb  = mbs / Sc;
        int m  = lane >> 2;
        int q  = lane & 3;
        int np = (q == 0) ? 5 : 4;
        const float* tb = preds + ((size_t)mbs * Cc + Pc) * HWc;
        const int* kpb = gt_kp + ((mb * Mc + m) * Pc) * 2;

        float gv[5], vv[5];
        float cnt = 0.0f, sum = 0.0f;
#pragma unroll
        for (int i = 0; i < 5; i++) {
            gv[i] = 0.0f; vv[i] = 0.0f;
            if (i < np) {
                int pp2 = q + 4 * i;
                int idx  = kpb[2 * pp2];
                float vis = (kpb[2 * pp2 + 1] > 0) ? 1.0f : 0.0f;
                float g = tb[idx];
                gv[i] = g; vv[i] = vis;
                cnt += vis; sum += vis * g;
            }
        }
        cnt += __shfl_xor_sync(0xffffffffu, cnt, 1);
        cnt += __shfl_xor_sync(0xffffffffu, cnt, 2);
        sum += __shfl_xor_sync(0xffffffffu, sum, 1);
        sum += __shfl_xor_sync(0xffffffffu, sum, 2);
        float valid = (cnt > 0.0f) ? 1.0f : 0.0f;
        float safe  = fmaxf(cnt, 1.0f);
        float mean  = sum / safe;
        float pp = 0.0f;
#pragma unroll
        for (int i = 0; i < 5; i++) {
            float d = gv[i] - mean;
            pp += d * d * vv[i];
        }
        pp += __shfl_xor_sync(0xffffffffu, pp, 1);
        pp += __shfl_xor_sync(0xffffffffu, pp, 2);
        float pull_m = (pp / safe) * valid;
        float num = valid, pullsum = pull_m;
#pragma unroll
        for (int o = 4; o <= 16; o <<= 1) {
            num     += __shfl_xor_sync(0xffffffffu, num, o);
            pullsum += __shfl_xor_sync(0xffffffffu, pullsum, o);
        }
        float rowsum = 0.0f;
#pragma unroll
        for (int jj = 0; jj < 2; jj++) {
            int j = q + 4 * jj;
            float mj = __shfl_sync(0xffffffffu, mean, j * 4);
            float vj = __shfl_sync(0xffffffffu, valid, j * 4);
            float d = mean - mj;
            rowsum += expf(-d * d) * valid * vj;
        }
        rowsum += __shfl_xor_sync(0xffffffffu, rowsum, 1);
        rowsum += __shfl_xor_sync(0xffffffffu, rowsum, 2);
        float pmsum = rowsum;
#pragma unroll
        for (int o = 4; o <= 16; o <<= 1)
            pmsum += __shfl_xor_sync(0xffffffffu, pmsum, o);
        if (lane == 0) {
            spush[mbs] = (pmsum - num) / ((num - 1.0f) * num + 1e-6f) * 0.5f;
            spull[mbs] = pullsum / (num + 1e-6f);
        }
    }
    __syncthreads();

    // --- tv & person_ids + det total ---
    double dacc = 0.0;
    for (int j = tid; j < BSc * NCH; j += 256) dacc += g_det_part[j];
    if (tid < BSc * Kc) {
        int tbs = tid / Kc;
        int tb  = tbs / Sc;
        int i  = g_topi[tid];
        int tp = i / HWc;
        int hw = i % HWc;
        int xi = hw / Wc;
        int yi = hw % Wc;
        g_tv[tid] = preds[((size_t)tbs * Cc + Pc) * HWc + i];
        float best = 3.4e38f; int bestm = 0;
        for (int m = 0; m < Mc; m++) {
            const float* sk = gt_sk + ((tb * Mc + m) * Pc + tp) * 3;
            float vp = (sk[2] == 1.0f) ? 256.0f : 0.0f;
            float d0 = vp + sk[1] - (float)xi;
            float d1 = vp + sk[2] - (float)yi;
            float d  = sqrtf(d0 * d0 + d1 * d1 + 1e-12f);
            if (d < best) { best = d; bestm = m; }
        }
        g_pid[tid] = bestm;
    }
    dred[tid] = dacc;
    __syncthreads();
    for (int o = 128; o > 0; o >>= 1) {
        if (tid < o) dred[tid] += dred[tid + o];
        __syncthreads();
    }
    if (tid == 0) {
        g_dettot = dred[0];
        double sp = 0.0, sl = 0.0;
        for (int j = 0; j < BSc; j++) { sp += (double)spush[j]; sl += (double)spull[j]; }
        g_pushpull[0] = sp;
        g_pushpull[1] = sl;
        g_cnt1 = 0;          // reset for graph replay
    }
}

// ============================================================
// Kernel 2: per-(bs,p) softmax sums + fused Huber; LAST block combines
// grid (Pc, BSc) = 136 blocks, 512 threads
// ============================================================
__global__ void __launch_bounds__(512) softhub_kernel(const float* __restrict__ preds,
                                                      const float* __restrict__ gt_sk,
                                                      float* __restrict__ out) {
    int p  = blockIdx.x;
    int bs = blockIdx.y;
    int tid = threadIdx.x;
    const float4* __restrict__ hm4 = (const float4*)(preds + ((size_t)bs * Cc + p) * HWc);
    const float4* __restrict__ tg4 = hm4 + (Pc * HWc / 4);

    const float C1 = 4.328085122666891f;    // 3 * log2(e)
    const float C2 = 18.033688011112047f;   // 12.5 * log2(e)
    const float TWOC2 = 36.067376022224094f;
    float hmax = fmaxf(g_cand_v[(bs * NCH + 2 * p) * Kc],
                       g_cand_v[(bs * NCH + 2 * p + 1) * Kc]);
    float L = C1 * hmax;

    float tv[Kc], tvq[Kc];
#pragma unroll
    for (int k = 0; k < Kc; k++) {
        float t = g_tv[bs * Kc + k];
        tv[k] = t;
        tvq[k] = -C2 * t * t;
    }

    float se[Kc], sx[Kc], sy[Kc];
#pragma unroll
    for (int k = 0; k < Kc; k++) { se[k] = 0.0f; sx[k] = 0.0f; sy[k] = 0.0f; }

#pragma unroll 2
    for (int j = 0; j < 8; j++) {
        int idx4 = tid + 512 * j;
        float4 h = hm4[idx4];
        float4 t = tg4[idx4];
        int e0 = 4 * idx4;
        float hs[4] = {h.x, h.y, h.z, h.w};
        float ts[4] = {t.x, t.y, t.z, t.w};
        float xf = (float)(e0 >> 7);
        float yb = (float)(e0 & 127);
#pragma unroll
        for (int c = 0; c < 4; c++) {
            float base = fmaf(C1, hs[c], -L);
            float A  = fmaf(ts[c] * (-C2), ts[c], base);  // base - C2*t^2
            float Bt = ts[c] * TWOC2;                      // 2*C2*t
            float yf = yb + (float)c;
#pragma unroll
            for (int k = 0; k < Kc; k++) {
                float l = fmaf(Bt, tv[k], A) + tvq[k];     // base - C2*(t-tv)^2
                float e = exp2f(l);
                se[k] += e;
                sx[k] = fmaf(e, xf, sx[k]);
                sy[k] = fmaf(e, yf, sy[k]);
            }
        }
    }

#pragma unroll
    for (int o = 16; o > 0; o >>= 1) {
#pragma unroll
        for (int k = 0; k < Kc; k++) {
            se[k] += __shfl_xor_sync(0xffffffffu, se[k], o);
            sx[k] += __shfl_xor_sync(0xffffffffu, sx[k], o);
            sy[k] += __shfl_xor_sync(0xffffffffu, sy[k], o);
        }
    }
    __shared__ float swarp[16][30];
    int w = tid >> 5;
    if ((tid & 31) == 0) {
#pragma unroll
        for (int k = 0; k < Kc; k++) {
            swarp[w][k]      = se[k];
            swarp[w][10 + k] = sx[k];
            swarp[w][20 + k] = sy[k];
        }
    }
    __syncthreads();
    __shared__ float tot[30];
    if (tid < 30) {
        float s = 0.0f;
#pragma unroll
        for (int ww = 0; ww < 16; ww++) s += swarp[ww][tid];
        tot[tid] = s;
    }
    __syncthreads();

    // fused Huber: thread k handles top-k index k
    __shared__ double shub[Kc];
    if (tid < Kc) {
        int k = tid;
        int b = bs >> 1;
        float seT = tot[k], sxT = tot[10 + k], syT = tot[20 + k];
        float inv = 1.0f / seT;
        float px = sxT * inv, py = syT * inv;
        int pid = g_pid[bs * Kc + k];
        const float* sk = gt_sk + ((b * Mc + pid) * Pc + p) * 3;
        float ex = sk[0] - px;
        float ey = sk[1] - py;
        float err = sqrtf(ex * ex + ey * ey + 1e-12f) * ((sk[2] > 0.0f) ? 1.0f : 0.0f);
        float a = fabsf(err);
        shub[k] = (double)((a < 0.1f) ? (err * err) : (0.1f * (a - 0.05f)));
    }
    __syncthreads();
    if (tid == 0) {
        double s = 0.0;
#pragma unroll
        for (int k = 0; k < Kc; k++) s += shub[k];
        g_hubpart[bs * Pc + p] = s;
    }

    // ================= last-block final combine =================
    __threadfence();
    __shared__ int isLast;
    if (tid == 0) {
        int c = atomicAdd(&g_cnt2, 1);
        isLast = (c == SOFT_NBLK - 1) ? 1 : 0;
    }
    __syncthreads();
    if (!isLast) return;
    __threadfence();

    double hacc = 0.0;
    for (int j = tid; j < BSc * Pc; j += 512) hacc += g_hubpart[j];
    __shared__ double hred[512];
    hred[tid] = hacc;
    __syncthreads();
    for (int o = 256; o > 0; o >>= 1) {
        if (tid < o) hred[tid] += hred[tid + o];
        __syncthreads();
    }
    if (tid == 0) {
        double det = g_dettot / (double)DET_N;
        double total = g_pushpull[0] / 8.0
                     + g_pushpull[1] / 8.0
                     + det
                     + 10.0 * hred[0] / (double)NITEM;
        out[0] = (float)total;
        g_cnt2 = 0;          // reset for graph replay
    }
}

// ============================================================
extern "C" void kernel_launch(void* const* d_in, const int* in_sizes, int n_in,
                              void* d_out, int out_size) {
    const float* preds       = (const float*)d_in[0];
    const float* gt_masks    = (const float*)d_in[1];
    const float* gt_heatmaps = (const float*)d_in[2];
    const float* gt_sk       = (const float*)d_in[3];
    const int*   gt_kp       = (const int*)d_in[4];

    scan_kernel<<<dim3(NCH, BSc), 256>>>(preds, gt_masks, gt_heatmaps, gt_sk, gt_kp);
    softhub_kernel<<<dim3(Pc, BSc), 512>>>(preds, gt_sk, (float*)d_out);
}